// round 16
// baseline (speedup 1.0000x reference)
#include <cuda_runtime.h>
#include <cuda_fp16.h>
#include <math.h>
#include <stdint.h>

#define T_ 1024
#define H_ 1024
#define I_ 512
#define E_ 64
#define S_ 2
#define G_ 8
#define TG_ 4
#define K_ 8
#define NEXP 66
#define ROUTED_ENTRIES (T_ * K_)
#define ENTRIES (ROUTED_ENTRIES + S_ * T_)
#define SLOTS (K_ + S_)

// ---- smem geometry (dynamic). M-tile = 64 rows ----
#define A_ST    144                 // bytes per A row (64 fp16 + pad)
#define A_STAGE 9216                // 64 rows
#define B_ST    272                 // bytes per B k-row (128 fp16 + pad)
#define B_STAGE 17408
#define OFF_A   1024
#define OFF_B   (1024 + 2 * A_STAGE)
#define MM_SMEM (1024 + 2 * A_STAGE + 2 * B_STAGE)   // 54272

// ---------------- device scratch ----------------
__device__ float g_logits[T_ * E_];
__device__ int   g_topk_idx[T_ * K_];
__device__ float g_topk_w[T_ * K_];
__device__ int   g_rank[T_ * K_];
__device__ int   g_cnt[NEXP];
__device__ int   g_off[NEXP];
__device__ int   g_etok[ENTRIES];
__device__ int   g_eslot[ENTRIES];
__device__ float g_ew[ENTRIES];
__device__ __half g_xh[T_ * H_];
__device__ __half g_hid[(size_t)ENTRIES * I_];
__device__ float g_contrib[(size_t)T_ * SLOTS * H_];

// ---------------- helpers ----------------
__device__ __forceinline__ uint32_t smem_u32(const void* p) {
    uint32_t a;
    asm("{ .reg .u64 t; cvta.to.shared.u64 t, %1; cvt.u32.u64 %0, t; }" : "=r"(a) : "l"(p));
    return a;
}
__device__ __forceinline__ void ldmat4(uint32_t r[4], uint32_t addr) {
    asm volatile("ldmatrix.sync.aligned.m8n8.x4.shared.b16 {%0,%1,%2,%3}, [%4];"
        : "=r"(r[0]), "=r"(r[1]), "=r"(r[2]), "=r"(r[3]) : "r"(addr));
}
__device__ __forceinline__ void ldmat2t(uint32_t r[2], uint32_t addr) {
    asm volatile("ldmatrix.sync.aligned.m8n8.x2.trans.shared.b16 {%0,%1}, [%2];"
        : "=r"(r[0]), "=r"(r[1]) : "r"(addr));
}
__device__ __forceinline__ void mma16816(float d[4], const uint32_t a[4], const uint32_t b[2]) {
    asm volatile("mma.sync.aligned.m16n8k16.row.col.f32.f16.f16.f32 "
        "{%0,%1,%2,%3}, {%4,%5,%6,%7}, {%8,%9}, {%0,%1,%2,%3};"
        : "+f"(d[0]), "+f"(d[1]), "+f"(d[2]), "+f"(d[3])
        : "r"(a[0]), "r"(a[1]), "r"(a[2]), "r"(a[3]), "r"(b[0]), "r"(b[1]));
}
#define CPA16(dst, src) \
    asm volatile("cp.async.cg.shared.global [%0], [%1], 16;" :: "r"(dst), "l"(src))
#define CPA_COMMIT() asm volatile("cp.async.commit_group;" ::: "memory")
#define CPA_WAIT()   asm volatile("cp.async.wait_group 0;" ::: "memory")

__device__ __forceinline__ uint32_t pkh(__half a, __half b) {
    __half2 t; t.x = a; t.y = b;
    return *reinterpret_cast<uint32_t*>(&t);
}
__device__ __forceinline__ uint2 cvt4h(float4 v) {
    return make_uint2(pkh(__float2half_rn(v.x), __float2half_rn(v.y)),
                      pkh(__float2half_rn(v.z), __float2half_rn(v.w)));
}

// ---------------- gate (+ fused x->fp16 conversion) ----------------
__global__ __launch_bounds__(256) void k_gate(const float* __restrict__ x,
                                              const float* __restrict__ gw) {
    if (blockIdx.x == 0 && threadIdx.x < E_) g_cnt[threadIdx.x] = 0;
    __shared__ float xs[16][64];
    __shared__ float ws[64][65];
    int tid = threadIdx.x;
    int t0 = blockIdx.x * 16;
    int e  = tid & 63;
    int ty = tid >> 6;
    float acc[4] = {0.f, 0.f, 0.f, 0.f};
    for (int k0 = 0; k0 < H_; k0 += 64) {
        #pragma unroll
        for (int j = 0; j < 4; j++) {
            int ii = tid + 256 * j;
            int r = ii >> 6, kk = ii & 63;
            xs[r][kk] = x[(size_t)(t0 + r) * H_ + k0 + kk];
        }
        #pragma unroll
        for (int j = 0; j < 16; j++) {
            int ii = tid + 256 * j;
            int ee = ii >> 6, kk = ii & 63;
            ws[kk][ee] = gw[(size_t)ee * H_ + k0 + kk];
        }
        __syncthreads();
        // fused: convert this 16x64 x-chunk to fp16
        {
            int r = tid >> 6, kk = (tid & 63) * 4;
            // 256 threads cover 16x64/4 = 256 quads... 16 rows * 16 quads = 256
            int rr = tid >> 4, cq = (tid & 15) * 4;
            float4 v = make_float4(xs[rr][cq], xs[rr][cq + 1], xs[rr][cq + 2], xs[rr][cq + 3]);
            *reinterpret_cast<uint2*>(g_xh + (size_t)(t0 + rr) * H_ + k0 + cq) = cvt4h(v);
            (void)r; (void)kk;
        }
        #pragma unroll 8
        for (int kk = 0; kk < 64; kk++) {
            float b = ws[kk][e];
            #pragma unroll
            for (int m = 0; m < 4; m++) acc[m] += xs[ty + 4 * m][kk] * b;
        }
        __syncthreads();
    }
    #pragma unroll
    for (int m = 0; m < 4; m++)
        g_logits[(size_t)(t0 + ty + 4 * m) * E_ + e] = acc[m];
}

__global__ void k_topk() {
    int t = blockIdx.x * blockDim.x + threadIdx.x;
    if (t >= T_) return;
    float lv[E_];
    #pragma unroll
    for (int e = 0; e < E_; e++) lv[e] = g_logits[(size_t)t * E_ + e];
    float cv[G_ * TG_];
    int   ce[G_ * TG_];
    #pragma unroll
    for (int g = 0; g < G_; g++) {
        float tmp[8];
        #pragma unroll
        for (int j = 0; j < 8; j++) tmp[j] = lv[g * 8 + j];
        #pragma unroll
        for (int r = 0; r < TG_; r++) {
            int bi = 0; float bv = tmp[0];
            #pragma unroll
            for (int j = 1; j < 8; j++)
                if (tmp[j] > bv) { bv = tmp[j]; bi = j; }
            cv[g * TG_ + r] = bv;
            ce[g * TG_ + r] = bi;
            tmp[bi] = -INFINITY;
        }
    }
    float tw[K_]; int tix[K_];
    float wsum = 0.f;
    #pragma unroll
    for (int r = 0; r < K_; r++) {
        int bi = 0; float bv = cv[0];
        #pragma unroll
        for (int j = 1; j < G_ * TG_; j++)
            if (cv[j] > bv) { bv = cv[j]; bi = j; }
        int grp = bi / TG_;
        tw[r]  = bv;
        tix[r] = grp * 8 + ce[bi];
        cv[bi] = -INFINITY;
        wsum  += bv;
    }
    float inv = 1.0f / (wsum + 1e-20f);
    #pragma unroll
    for (int r = 0; r < K_; r++) {
        g_topk_idx[t * K_ + r] = tix[r];
        g_topk_w[t * K_ + r]   = tw[r] * inv;
        g_rank[t * K_ + r]     = atomicAdd(&g_cnt[tix[r]], 1);
    }
}

// parallel scatter: 8 blocks x 128 threads, per-block local scan
__global__ __launch_bounds__(128) void k_scatter() {
    __shared__ int soff[E_];
    int tid = threadIdx.x;
    if (tid == 0) {
        int run = 0;
        #pragma unroll
        for (int e = 0; e < E_; e++) { soff[e] = run; run += g_cnt[e]; }
    }
    __syncthreads();
    if (blockIdx.x == 0) {
        if (tid < E_) g_off[tid] = soff[tid];
        if (tid == E_)     { g_off[E_]     = ROUTED_ENTRIES;      g_cnt[E_]     = T_; }
        if (tid == E_ + 1) { g_off[E_ + 1] = ROUTED_ENTRIES + T_; g_cnt[E_ + 1] = T_; }
    }
    int t = blockIdx.x * 128 + tid;
    #pragma unroll
    for (int r = 0; r < K_; r++) {
        int i = t * K_ + r;
        int e = g_topk_idx[i];
        int p = soff[e] + g_rank[i];
        g_etok[p]  = t;
        g_eslot[p] = r;
        g_ew[p]    = g_topk_w[i];
    }
    #pragma unroll
    for (int s = 0; s < S_; s++) {
        int p = ROUTED_ENTRIES + s * T_ + t;
        g_etok[p]  = t;
        g_eslot[p] = K_ + s;
        g_ew[p]    = 1.0f;
    }
}

// ---------------- pipelined mainloop pieces (M-tile 64) ----------------
#define MM_A_ISSUE(Asrc, AST, s, k0)                                              \
    _Pragma("unroll")                                                             \
    for (int j = 0; j < 2; j++) {                                                 \
        int idx = tid + 256 * j;                                                  \
        int row = idx >> 3, seg = idx & 7;                                        \
        size_t go = (size_t)ridx[row] * (AST) + (k0) + seg * 8;                   \
        uint32_t so = sb + OFF_A + (s) * A_STAGE +                                \
            (uint32_t)(row * A_ST + seg * 16);                                    \
        CPA16(so, (Asrc) + go);                                                   \
    }

#define MM_B_STORE_HALF(s, h)                                                     \
    _Pragma("unroll")                                                             \
    for (int j = 0; j < 4; j++) {                                                 \
        int idx = tid + 256 * (j + 4 * (h));                                      \
        int kk = idx >> 5, c4 = (idx & 31) * 4;                                   \
        char* bp = smem + OFF_B + (s) * B_STAGE + kk * B_ST + c4 * 2;             \
        *reinterpret_cast<uint2*>(bp) = cvt4h(breg[j]);                           \
    }

#define MM_COMPUTE(s, ks0, ks1)                                                   \
    _Pragma("unroll")                                                             \
    for (int ks = (ks0); ks < (ks1); ks++) {                                      \
        uint32_t aa[2][4], bb[4][2];                                              \
        _Pragma("unroll")                                                         \
        for (int mf = 0; mf < 2; mf++) {                                          \
            uint32_t ad = sb + OFF_A + (s) * A_STAGE +                            \
                (uint32_t)((wm + mf * 16 + a_r) * A_ST + (ks * 16 + a_c) * 2);    \
            ldmat4(aa[mf], ad);                                                   \
        }                                                                         \
        _Pragma("unroll")                                                         \
        for (int nf = 0; nf < 4; nf++) {                                          \
            uint32_t bd = sb + OFF_B + (s) * B_STAGE +                            \
                (uint32_t)((ks * 16 + b_r) * B_ST + (wn + nf * 8) * 2);           \
            ldmat2t(bb[nf], bd);                                                  \
        }                                                                         \
        _Pragma("unroll")                                                         \
        for (int mf = 0; mf < 2; mf++)                                            \
            _Pragma("unroll")                                                     \
            for (int nf = 0; nf < 4; nf++)                                        \
                mma16816(acc[mf][nf], aa[mf], bb[nf]);                            \
    }

// ---------------- GEMM1: gate_up + fused SiLU -> hidden fp16 ----------------
// bid = e*128 + tile*8 + col (col fastest). M-tile 64, up to 16 tiles.
__global__ __launch_bounds__(256, 2) void k_mm1(const float* __restrict__ w_gu,
                                                const float* __restrict__ s_gu) {
    int bid  = blockIdx.x;
    int gb   = (bid & 7) * 64;
    int tile = (bid >> 3) & 15;
    int e    = bid >> 7;
    int n = g_cnt[e];
    int r0 = tile * 64;
    if (r0 >= n) return;
    int base = g_off[e];
    const float* B = (e < E_) ? (w_gu + (size_t)e * (H_ * 2 * I_))
                              : (s_gu + (size_t)(e - E_) * (H_ * 2 * I_));

    extern __shared__ __align__(16) char smem[];
    uint32_t sb = smem_u32(smem);
    int tid = threadIdx.x, wid = tid >> 5, lane = tid & 31;
    int* ridx = reinterpret_cast<int*>(smem);
    if (tid < 64) {
        int rr = r0 + tid;
        ridx[tid] = g_etok[base + ((rr < n) ? rr : (n - 1))];
    }
    __syncthreads();

    int wm = (wid & 1) * 32;
    int wn = (wid >> 1) * 32;
    int a_r = lane & 15, a_c = (lane >> 4) * 8;
    int b_r = (lane & 7) + ((lane >> 3) & 1) * 8;

    float acc[2][4][4];
    #pragma unroll
    for (int mf = 0; mf < 2; mf++)
        #pragma unroll
        for (int nf = 0; nf < 4; nf++)
            #pragma unroll
            for (int v = 0; v < 4; v++) acc[mf][nf][v] = 0.f;

    float4 breg[4];
    const int NC = H_ / 64;

    MM_A_ISSUE(g_xh, H_, 0, 0);
    CPA_COMMIT();
    #pragma unroll
    for (int h = 0; h < 2; h++) {
        #pragma unroll
        for (int j = 0; j < 4; j++) {
            int idx = tid + 256 * (j + 4 * h);
            int kk = idx >> 5, c4 = (idx & 31) * 4;
            int src = (c4 < 64) ? (gb + c4) : (448 + gb + c4);
            breg[j] = *reinterpret_cast<const float4*>(B + (size_t)kk * (2 * I_) + src);
        }
        MM_B_STORE_HALF(0, h);
    }
    CPA_WAIT();
    __syncthreads();

    for (int kc = 0; kc < NC; kc++) {
        int nxt = kc + 1;
        int cs = kc & 1, ns = nxt & 1;
        if (nxt < NC) {
            MM_A_ISSUE(g_xh, H_, ns, nxt * 64);
            CPA_COMMIT();
            #pragma unroll
            for (int j = 0; j < 4; j++) {
                int idx = tid + 256 * j;
                int kk = idx >> 5, c4 = (idx & 31) * 4;
                int src = (c4 < 64) ? (gb + c4) : (448 + gb + c4);
                breg[j] = *reinterpret_cast<const float4*>(
                    B + (size_t)(nxt * 64 + kk) * (2 * I_) + src);
            }
        }
        MM_COMPUTE(cs, 0, 2);
        if (nxt < NC) {
            MM_B_STORE_HALF(ns, 0);
            #pragma unroll
            for (int j = 0; j < 4; j++) {
                int idx = tid + 256 * (j + 4);
                int kk = idx >> 5, c4 = (idx & 31) * 4;
                int src = (c4 < 64) ? (gb + c4) : (448 + gb + c4);
                breg[j] = *reinterpret_cast<const float4*>(
                    B + (size_t)(nxt * 64 + kk) * (2 * I_) + src);
            }
        }
        MM_COMPUTE(cs, 2, 4);
        if (nxt < NC) {
            CPA_WAIT();
            MM_B_STORE_HALF(ns, 1);
        }
        __syncthreads();
    }

    // epilogue: smem transpose, SiLU, fp16 hidden
    float* otile = reinterpret_cast<float*>(smem + 1024);   // 64 x pitch 132
    #pragma unroll
    for (int mf = 0; mf < 2; mf++) {
        #pragma unroll
        for (int hf = 0; hf < 2; hf++) {
            int row = wm + mf * 16 + (lane >> 2) + hf * 8;
            #pragma unroll
            for (int nf = 0; nf < 4; nf++) {
                int col = wn + nf * 8 + (lane & 3) * 2;
                otile[row * 132 + col]     = acc[mf][nf][hf * 2];
                otile[row * 132 + col + 1] = acc[mf][nf][hf * 2 + 1];
            }
        }
    }
    __syncthreads();
    int nrows = n - r0;
    #pragma unroll
    for (int j = 0; j < 4; j++) {
        int idx = tid + 256 * j;        // 1024 = 64 rows x 16 col-groups
        int row = idx >> 4;
        int cg  = (idx & 15) * 4;
        if (row < nrows) {
            float4 g = *reinterpret_cast<const float4*>(otile + row * 132 + cg);
            float4 u = *reinterpret_cast<const float4*>(otile + row * 132 + 64 + cg);
            float4 h;
            h.x = g.x / (1.0f + expf(-g.x)) * u.x;
            h.y = g.y / (1.0f + expf(-g.y)) * u.y;
            h.z = g.z / (1.0f + expf(-g.z)) * u.z;
            h.w = g.w / (1.0f + expf(-g.w)) * u.w;
            size_t ep = (size_t)(base + r0 + row);
            *reinterpret_cast<uint2*>(g_hid + ep * I_ + gb + cg) = cvt4h(h);
        }
    }
}

// ---------------- GEMM2: down, weighted -> contrib ----------------
__global__ __launch_bounds__(256, 2) void k_mm2(const float* __restrict__ w_d,
                                                const float* __restrict__ s_d) {
    int bid  = blockIdx.x;
    int nb   = (bid & 7) * 128;
    int tile = (bid >> 3) & 15;
    int e    = bid >> 7;
    int n = g_cnt[e];
    int r0 = tile * 64;
    if (r0 >= n) return;
    int base = g_off[e];
    const float* B = (e < E_) ? (w_d + (size_t)e * (I_ * H_))
                              : (s_d + (size_t)(e - E_) * (I_ * H_));

    extern __shared__ __align__(16) char smem[];
    uint32_t sb = smem_u32(smem);
    int tid = threadIdx.x, wid = tid >> 5, lane = tid & 31;
    int* ridx = reinterpret_cast<int*>(smem);
    if (tid < 64) {
        int rr = r0 + tid;
        ridx[tid] = base + ((rr < n) ? rr : (n - 1));
    }
    __syncthreads();

    int wm = (wid & 1) * 32;
    int wn = (wid >> 1) * 32;
    int a_r = lane & 15, a_c = (lane >> 4) * 8;
    int b_r = (lane & 7) + ((lane >> 3) & 1) * 8;

    float acc[2][4][4];
    #pragma unroll
    for (int mf = 0; mf < 2; mf++)
        #pragma unroll
        for (int nf = 0; nf < 4; nf++)
            #pragma unroll
            for (int v = 0; v < 4; v++) acc[mf][nf][v] = 0.f;

    float4 breg[4];
    const int NC = I_ / 64;

    MM_A_ISSUE(g_hid, I_, 0, 0);
    CPA_COMMIT();
    #pragma unroll
    for (int h = 0; h < 2; h++) {
        #pragma unroll
        for (int j = 0; j < 4; j++) {
            int idx = tid + 256 * (j + 4 * h);
            int kk = idx >> 5, c4 = (idx & 31) * 4;
            breg[j] = *reinterpret_cast<const float4*>(B + (size_t)kk * H_ + nb + c4);
        }
        MM_B_STORE_HALF(0, h);
    }
    CPA_WAIT();
    __syncthreads();

    for (int kc = 0; kc < NC; kc++) {
        int nxt = kc + 1;
        int cs = kc & 1, ns = nxt & 1;
        if (nxt < NC) {
            MM_A_ISSUE(g_hid, I_, ns, nxt * 64);
            CPA_COMMIT();
            #pragma unroll
            for (int j = 0; j < 4; j++) {
                int idx = tid + 256 * j;
                int kk = idx >> 5, c4 = (idx & 31) * 4;
                breg[j] = *reinterpret_cast<const float4*>(
                    B + (size_t)(nxt * 64 + kk) * H_ + nb + c4);
            }
        }
        MM_COMPUTE(cs, 0, 2);
        if (nxt < NC) {
            MM_B_STORE_HALF(ns, 0);
            #pragma unroll
            for (int j = 0; j < 4; j++) {
                int idx = tid + 256 * (j + 4);
                int kk = idx >> 5, c4 = (idx & 31) * 4;
                breg[j] = *reinterpret_cast<const float4*>(
                    B + (size_t)(nxt * 64 + kk) * H_ + nb + c4);
            }
        }
        MM_COMPUTE(cs, 2, 4);
        if (nxt < NC) {
            CPA_WAIT();
            MM_B_STORE_HALF(ns, 1);
        }
        __syncthreads();
    }

    int nrows = n - r0;
    #pragma unroll
    for (int mf = 0; mf < 2; mf++) {
        int rl = wm + mf * 16 + (lane >> 2);
        #pragma unroll
        for (int hf = 0; hf < 2; hf++) {
            int row = rl + hf * 8;
            if (row < nrows) {
                int ep = base + r0 + row;
                int tok  = g_etok[ep];
                int slot = g_eslot[ep];
                float w  = g_ew[ep];
                float* dst = g_contrib + ((size_t)tok * SLOTS + slot) * H_;
                #pragma unroll
                for (int nf = 0; nf < 4; nf++) {
                    int col = nb + wn + nf * 8 + (lane & 3) * 2;
                    *reinterpret_cast<float2*>(dst + col) =
                        make_float2(acc[mf][nf][hf * 2] * w, acc[mf][nf][hf * 2 + 1] * w);
                }
            }
        }
    }
}

// ---------------- deterministic 10-slot reduce ----------------
__global__ void k_reduce(float* __restrict__ out) {
    int idx = blockIdx.x * 256 + threadIdx.x;
    int t = idx >> 10;
    int h = idx & 1023;
    const float* c = g_contrib + (size_t)t * SLOTS * H_ + h;
    float s = 0.f;
    #pragma unroll
    for (int j = 0; j < SLOTS; j++) s += c[(size_t)j * H_];
    out[idx] = s;
}

// ---------------- launch ----------------
extern "C" void kernel_launch(void* const* d_in, const int* in_sizes, int n_in,
                              void* d_out, int out_size) {
    const float* x      = (const float*)d_in[0];
    const float* gate_w = (const float*)d_in[1];
    const float* w_gu   = (const float*)d_in[2];
    const float* w_d    = (const float*)d_in[3];
    const float* s_gu   = (const float*)d_in[4];
    const float* s_d    = (const float*)d_in[5];
    float* out = (float*)d_out;

    cudaFuncSetAttribute(k_mm1, cudaFuncAttributeMaxDynamicSharedMemorySize, MM_SMEM);
    cudaFuncSetAttribute(k_mm2, cudaFuncAttributeMaxDynamicSharedMemorySize, MM_SMEM);

    k_gate<<<T_ / 16, 256>>>(x, gate_w);
    k_topk<<<16, 64>>>();
    k_scatter<<<8, 128>>>();
    k_mm1<<<NEXP * 128, 256, MM_SMEM>>>(w_gu, s_gu);
    k_mm2<<<NEXP * 128, 256, MM_SMEM>>>(w_d, s_d);
    k_reduce<<<(T_ * H_) / 256, 256>>>(out);
}